// round 7
// baseline (speedup 1.0000x reference)
#include <cuda_runtime.h>

#define NB     256      // batches
#define NQ     1000     // queries
#define NC     80       // classes
#define QC     80000    // NQ*NC
#define K      300      // top-k
#define NV     (QC / 4) // 20000 float4 per batch

#define SLICES    8
#define SLICE_F4  (NV / SLICES)   // 2500 float4 per slice
#define SLICE_CAP 512
#define CAPT      4096            // sort buffer (= SLICES*SLICE_CAP)

#define NTH1  256   // scan kernel threads
#define NTH2  512   // sort kernel threads

#define THRESH 2.45f   // P(N(0,1)>2.45) ~ 0.71% -> ~571 cands/batch

// global scratch (allowed: __device__ arrays, no allocation)
__device__ unsigned long long g_cand[NB][SLICES][SLICE_CAP];
__device__ unsigned           g_scnt[NB][SLICES];

// order-preserving float -> uint key (larger key == larger float)
__device__ __forceinline__ unsigned key_of(float x) {
    unsigned u = __float_as_uint(x);
    return (u & 0x80000000u) ? ~u : (u | 0x80000000u);
}
__device__ __forceinline__ float val_of(unsigned k) {
    unsigned u = (k & 0x80000000u) ? (k ^ 0x80000000u) : ~k;
    return __uint_as_float(u);
}

// ---------------- kernel 1: sliced threshold scan ----------------
__global__ __launch_bounds__(NTH1)
void scan_kernel(const float* __restrict__ logits)
{
    __shared__ unsigned s_cnt;
    const int b   = blockIdx.x >> 3;        // batch
    const int s   = blockIdx.x & 7;         // slice
    const int tid = threadIdx.x;

    if (tid == 0) s_cnt = 0;
    __syncthreads();

    const float4* base = (const float4*)(logits + (size_t)b * QC) + s * SLICE_F4;

    #pragma unroll 5
    for (int i = tid; i < SLICE_F4; i += NTH1) {
        float4 v = base[i];
        float m01 = fmaxf(v.x, v.y);
        float m23 = fmaxf(v.z, v.w);
        if (fmaxf(m01, m23) > THRESH) {          // rare (~2.8% of iters)
            float xs[4] = {v.x, v.y, v.z, v.w};
            #pragma unroll
            for (int j = 0; j < 4; j++) {
                if (xs[j] > THRESH) {
                    unsigned p = atomicAdd(&s_cnt, 1u);
                    if (p < SLICE_CAP) {
                        unsigned idx = 4u * (unsigned)(s * SLICE_F4 + i) + (unsigned)j;
                        g_cand[b][s][p] = ((unsigned long long)key_of(xs[j]) << 32)
                                        | (unsigned long long)(~idx);
                    }
                }
            }
        }
    }
    __syncthreads();
    if (tid == 0) g_scnt[b][s] = s_cnt;
}

// ---------------- kernel 2: gather + sort + epilogue ----------------
__global__ __launch_bounds__(NTH2)
void sort_kernel(const float* __restrict__ logits,
                 const float* __restrict__ boxes,
                 const float* __restrict__ sizes,
                 float* __restrict__ out)
{
    __shared__ unsigned long long cand[CAPT];
    __shared__ unsigned offs[SLICES + 1];
    __shared__ unsigned cnts[SLICES];
    __shared__ int      s_bad;
    __shared__ unsigned wcnt[NTH2 / 32];

    const int b    = blockIdx.x;
    const int tid  = threadIdx.x;
    const int wid  = tid >> 5;
    unsigned M;

    if (tid == 0) {
        unsigned sum = 0; int bad = 0;
        #pragma unroll
        for (int s = 0; s < SLICES; s++) {
            unsigned c = g_scnt[b][s];
            if (c > SLICE_CAP) bad = 1;
            cnts[s] = min(c, (unsigned)SLICE_CAP);
            offs[s] = sum;
            sum += cnts[s];
        }
        offs[SLICES] = sum;
        if (sum < K) bad = 1;
        s_bad = bad;
    }
    __syncthreads();

    if (!s_bad) {
        // gather candidate slices into contiguous smem
        #pragma unroll
        for (int s = 0; s < SLICES; s++) {
            unsigned c = cnts[s], o = offs[s];
            for (unsigned i = tid; i < c; i += NTH2)
                cand[o + i] = g_cand[b][s][i];
        }
        M = offs[SLICES];
        __syncthreads();
    } else {
        // fallback: full-batch bisection scan (correct for any distribution)
        const float4* base = (const float4*)(logits + (size_t)b * QC);
        const int lane = tid & 31;
        unsigned lo_key = 0u, hi_key = 0xFFFFFFFFu;
        unsigned cur = key_of(THRESH);
        const unsigned CAP_W = CAPT / (NTH2 / 32);   // 256 per warp
        M = 0;
        for (int attempt = 0; attempt < 34; attempt++) {
            if (tid < NTH2 / 32) wcnt[tid] = 0;
            __syncthreads();
            const float t = val_of(cur);
            for (int i = tid; i < NV; i += NTH2) {
                float4 v = base[i];
                float m01 = fmaxf(v.x, v.y);
                float m23 = fmaxf(v.z, v.w);
                if (fmaxf(m01, m23) > t) {
                    float xs[4] = {v.x, v.y, v.z, v.w};
                    #pragma unroll
                    for (int j = 0; j < 4; j++) {
                        if (xs[j] > t) {
                            unsigned p = atomicAdd(&wcnt[wid], 1u);
                            if (p < CAP_W) {
                                unsigned idx = 4u * (unsigned)i + (unsigned)j;
                                cand[wid * CAP_W + p] =
                                    ((unsigned long long)key_of(xs[j]) << 32)
                                  | (unsigned long long)(~idx);
                            }
                        }
                    }
                }
            }
            __syncthreads();
            if (tid == 0) {
                unsigned sum = 0; int ovf = 0;
                #pragma unroll
                for (int w = 0; w < NTH2 / 32; w++) {
                    if (wcnt[w] > CAP_W) ovf = 1;
                    sum += min(wcnt[w], CAP_W);
                }
                offs[0] = sum; s_bad = ovf;
            }
            __syncthreads();
            unsigned tot = offs[0]; int ovf = s_bad;
            if (!ovf && tot >= K) { M = tot; break; }
            if (ovf)  { lo_key = cur; cur = cur + ((hi_key - cur) >> 1); }
            else      { hi_key = cur; cur = lo_key + ((cur - lo_key) >> 1); }
            __syncthreads();
        }
        // compact warp slices (register-staged)
        __syncthreads();
        if (tid == 0) {
            unsigned sum = 0;
            #pragma unroll
            for (int w = 0; w < NTH2 / 32; w++) {
                cnts[0] = 0; // unused
                offs[0] = 0;
            }
            // reuse offs via serial pass stored into wcnt-prefix in offs? use cand-safe path:
        }
        __syncthreads();
        // simple serial-offset compaction: thread 0 computes warp offsets into offs[] (max 16 warps)
        __shared__ unsigned woff[NTH2 / 32 + 1];
        if (tid == 0) {
            unsigned sum = 0;
            #pragma unroll
            for (int w = 0; w < NTH2 / 32; w++) {
                woff[w] = sum;
                sum += min(wcnt[w], CAP_W);
            }
            woff[NTH2 / 32] = sum;
        }
        __syncthreads();
        {
            const int lane2 = tid & 31;
            unsigned cnt = min(wcnt[wid], CAP_W);
            unsigned long long rr[CAPT / NTH2];   // 8
            #pragma unroll
            for (int k = 0; k < CAPT / NTH2; k++) {
                unsigned s = (unsigned)lane2 + 32u * k;
                if (s < cnt) rr[k] = cand[wid * CAP_W + s];
            }
            __syncthreads();
            unsigned dst = woff[wid];
            #pragma unroll
            for (int k = 0; k < CAPT / NTH2; k++) {
                unsigned s = (unsigned)lane2 + 32u * k;
                if (s < cnt) cand[dst + s] = rr[k];
            }
        }
        __syncthreads();
        if (tid == 0) offs[SLICES] = 0; // keep offs defined
        M = 0;
        {
            // recompute M from woff on all threads (broadcast via smem)
            __syncthreads();
            M = woff[NTH2 / 32];
        }
        __syncthreads();
    }

    if (M > CAPT) M = CAPT;

    // ---- pad to pow2, bitonic sort descending ----
    unsigned n = 512;
    while (n < M) n <<= 1;   // <= 4096
    for (unsigned i = M + tid; i < n; i += NTH2) cand[i] = 0ull;
    __syncthreads();

    for (unsigned kk = 2; kk <= n; kk <<= 1) {
        for (unsigned j = kk >> 1; j > 0; j >>= 1) {
            for (unsigned i = tid; i < n; i += NTH2) {
                unsigned l = i ^ j;
                if (l > i) {
                    unsigned long long a = cand[i];
                    unsigned long long c = cand[l];
                    bool desc = ((i & kk) == 0);
                    if (desc ? (a < c) : (a > c)) {
                        cand[i] = c; cand[l] = a;
                    }
                }
            }
            __syncthreads();
        }
    }

    // ---- epilogue: top K -> labels, boxes, scores ----
    if (tid < K) {
        unsigned long long comp = cand[tid];
        unsigned kk  = (unsigned)(comp >> 32);
        unsigned idx = ~(unsigned)comp;
        float x = val_of(kk);
        float score = 1.0f / (1.0f + expf(-x));
        int label = (int)(idx % NC);
        int q     = (int)(idx / NC);

        float4 bx = ((const float4*)(boxes + ((size_t)b * NQ + q) * 4))[0];
        float w = sizes[2 * b], h = sizes[2 * b + 1];
        float hw = 0.5f * bx.z, hh = 0.5f * bx.w;

        int o = b * K + tid;
        out[o] = (float)label;                     // labels [B,K]
        float* ob = out + NB * K + (size_t)o * 4;  // boxes  [B,K,4]
        ob[0] = (bx.x - hw) * w;
        ob[1] = (bx.y - hh) * h;
        ob[2] = (bx.x + hw) * w;
        ob[3] = (bx.y + hh) * h;
        out[(size_t)NB * K * 5 + o] = score;       // scores [B,K]
    }
}

extern "C" void kernel_launch(void* const* d_in, const int* in_sizes, int n_in,
                              void* d_out, int out_size) {
    const float* logits = (const float*)d_in[0];
    const float* boxes  = (const float*)d_in[1];
    const float* sizes  = (const float*)d_in[2];
    float* out = (float*)d_out;
    scan_kernel<<<NB * SLICES, NTH1>>>(logits);
    sort_kernel<<<NB, NTH2>>>(logits, boxes, sizes, out);
}

// round 8
// speedup vs baseline: 1.0570x; 1.0570x over previous
#include <cuda_runtime.h>

#define NB     256      // batches
#define NQ     1000     // queries
#define NC     80       // classes
#define QC     80000    // NQ*NC
#define K      300      // top-k
#define NV     (QC / 4) // 20000 float4 per batch

#define SLICES    8
#define SLICE_F4  (NV / SLICES)   // 2500 float4 per slice
#define SLICE_CAP 384
#define RCAP      1024            // rank-selection buffer capacity

#define NTH1  256   // scan kernel threads
#define NTH2  512   // rank kernel threads

#define THRESH 2.576f   // P(N(0,1)>2.576) ~ 0.5% -> ~400 cands/batch

// global scratch (allowed: __device__ arrays, no allocation)
__device__ unsigned long long g_cand[NB][SLICES][SLICE_CAP];
__device__ unsigned           g_scnt[NB][SLICES];

// order-preserving float -> uint key (larger key == larger float)
__device__ __forceinline__ unsigned key_of(float x) {
    unsigned u = __float_as_uint(x);
    return (u & 0x80000000u) ? ~u : (u | 0x80000000u);
}
__device__ __forceinline__ float val_of(unsigned k) {
    unsigned u = (k & 0x80000000u) ? (k ^ 0x80000000u) : ~k;
    return __uint_as_float(u);
}

// ---------------- kernel 1: sliced threshold scan (at HBM roofline) ----------------
__global__ __launch_bounds__(NTH1)
void scan_kernel(const float* __restrict__ logits)
{
    __shared__ unsigned s_cnt;
    const int b   = blockIdx.x >> 3;        // batch
    const int s   = blockIdx.x & 7;         // slice
    const int tid = threadIdx.x;

    if (tid == 0) s_cnt = 0;
    __syncthreads();

    const float4* base = (const float4*)(logits + (size_t)b * QC) + s * SLICE_F4;

    #pragma unroll 5
    for (int i = tid; i < SLICE_F4; i += NTH1) {
        float4 v = base[i];
        float m01 = fmaxf(v.x, v.y);
        float m23 = fmaxf(v.z, v.w);
        if (fmaxf(m01, m23) > THRESH) {          // rare (~2% of iters)
            float xs[4] = {v.x, v.y, v.z, v.w};
            #pragma unroll
            for (int j = 0; j < 4; j++) {
                if (xs[j] > THRESH) {
                    unsigned p = atomicAdd(&s_cnt, 1u);
                    if (p < SLICE_CAP) {
                        unsigned idx = 4u * (unsigned)(s * SLICE_F4 + i) + (unsigned)j;
                        g_cand[b][s][p] = ((unsigned long long)key_of(xs[j]) << 32)
                                        | (unsigned long long)(~idx);
                    }
                }
            }
        }
    }
    __syncthreads();
    if (tid == 0) g_scnt[b][s] = s_cnt;
}

// ---------------- kernel 2: gather + rank-select + epilogue ----------------
__global__ __launch_bounds__(NTH2)
void rank_kernel(const float* __restrict__ logits,
                 const float* __restrict__ boxes,
                 const float* __restrict__ sizes,
                 float* __restrict__ out)
{
    __shared__ unsigned long long cand[RCAP];
    __shared__ unsigned offs[SLICES + 1];
    __shared__ unsigned cnts[SLICES];
    __shared__ int      s_bad;
    __shared__ unsigned s_cnt;

    const int b   = blockIdx.x;
    const int tid = threadIdx.x;
    unsigned M;

    if (tid == 0) {
        unsigned sum = 0; int bad = 0;
        #pragma unroll
        for (int s = 0; s < SLICES; s++) {
            unsigned c = g_scnt[b][s];
            if (c > SLICE_CAP) bad = 1;
            cnts[s] = min(c, (unsigned)SLICE_CAP);
            offs[s] = sum;
            sum += cnts[s];
        }
        offs[SLICES] = sum;
        if (sum < K || sum > RCAP) bad = 1;
        s_bad = bad;
    }
    __syncthreads();

    if (!s_bad) {
        // gather candidate slices into contiguous smem (tiny; L2-resident)
        #pragma unroll
        for (int s = 0; s < SLICES; s++) {
            unsigned c = cnts[s], o = offs[s];
            for (unsigned i = tid; i < c; i += NTH2)
                cand[o + i] = g_cand[b][s][i];
        }
        M = offs[SLICES];
        __syncthreads();
    } else {
        // fallback: full-batch bisection rescan (correct for any distribution)
        const float4* base = (const float4*)(logits + (size_t)b * QC);
        unsigned lo_key = 0u, hi_key = 0xFFFFFFFFu;
        unsigned cur = key_of(THRESH);
        M = 0;
        for (int attempt = 0; attempt < 34; attempt++) {
            if (tid == 0) s_cnt = 0;
            __syncthreads();
            const float t = val_of(cur);
            for (int i = tid; i < NV; i += NTH2) {
                float4 v = base[i];
                float m01 = fmaxf(v.x, v.y);
                float m23 = fmaxf(v.z, v.w);
                if (fmaxf(m01, m23) > t) {
                    float xs[4] = {v.x, v.y, v.z, v.w};
                    #pragma unroll
                    for (int j = 0; j < 4; j++) {
                        if (xs[j] > t) {
                            unsigned p = atomicAdd(&s_cnt, 1u);
                            if (p < RCAP) {
                                unsigned idx = 4u * (unsigned)i + (unsigned)j;
                                cand[p] = ((unsigned long long)key_of(xs[j]) << 32)
                                        | (unsigned long long)(~idx);
                            }
                        }
                    }
                }
            }
            __syncthreads();
            unsigned tot = s_cnt;
            if (tot >= K && tot <= RCAP) { M = tot; break; }
            __syncthreads();
            if (tot > RCAP) { lo_key = cur; cur = cur + ((hi_key - cur) >> 1); }
            else            { hi_key = cur; cur = lo_key + ((cur - lo_key) >> 1); }
        }
        if (M == 0) M = min(s_cnt, (unsigned)RCAP);  // exhausted: clamp
        __syncthreads();
    }

    // ---- rank selection: rank[i] = #{j : cand[j] > cand[i]} (keys unique) ----
    unsigned long long my0 = 0ull, my1 = 0ull;
    const unsigned i0 = tid;
    const unsigned i1 = tid + NTH2;
    const bool a0 = (i0 < M);
    const bool a1 = (i1 < M);
    if (a0) my0 = cand[i0];
    if (a1) my1 = cand[i1];

    unsigned r0 = 0, r1 = 0;
    {
        unsigned j = 0;
        const unsigned M4 = M & ~3u;
        for (; j < M4; j += 4) {
            unsigned long long v0 = cand[j + 0];
            unsigned long long v1 = cand[j + 1];
            unsigned long long v2 = cand[j + 2];
            unsigned long long v3 = cand[j + 3];
            r0 += (v0 > my0) + (v1 > my0) + (v2 > my0) + (v3 > my0);
            r1 += (v0 > my1) + (v1 > my1) + (v2 > my1) + (v3 > my1);
        }
        for (; j < M; j++) {
            unsigned long long v = cand[j];
            r0 += (v > my0);
            r1 += (v > my1);
        }
    }

    // ---- epilogue: candidates with rank < K scatter directly to output ----
    const float w = sizes[2 * b], h = sizes[2 * b + 1];
    #pragma unroll
    for (int half = 0; half < 2; half++) {
        bool act = half ? (a1 && r1 < K) : (a0 && r0 < K);
        if (act) {
            unsigned long long comp = half ? my1 : my0;
            unsigned rank = half ? r1 : r0;
            unsigned kk  = (unsigned)(comp >> 32);
            unsigned idx = ~(unsigned)comp;
            float x = val_of(kk);
            float score = 1.0f / (1.0f + expf(-x));
            int label = (int)(idx % NC);
            int q     = (int)(idx / NC);

            float4 bx = ((const float4*)(boxes + ((size_t)b * NQ + q) * 4))[0];
            float hw = 0.5f * bx.z, hh = 0.5f * bx.w;

            int o = b * K + (int)rank;
            out[o] = (float)label;                     // labels [B,K]
            float* ob = out + NB * K + (size_t)o * 4;  // boxes  [B,K,4]
            ob[0] = (bx.x - hw) * w;
            ob[1] = (bx.y - hh) * h;
            ob[2] = (bx.x + hw) * w;
            ob[3] = (bx.y + hh) * h;
            out[(size_t)NB * K * 5 + o] = score;       // scores [B,K]
        }
    }
}

extern "C" void kernel_launch(void* const* d_in, const int* in_sizes, int n_in,
                              void* d_out, int out_size) {
    const float* logits = (const float*)d_in[0];
    const float* boxes  = (const float*)d_in[1];
    const float* sizes  = (const float*)d_in[2];
    float* out = (float*)d_out;
    scan_kernel<<<NB * SLICES, NTH1>>>(logits);
    rank_kernel<<<NB, NTH2>>>(logits, boxes, sizes, out);
}

// round 9
// speedup vs baseline: 1.5714x; 1.4867x over previous
#include <cuda_runtime.h>

#define NB     256      // batches
#define NQ     1000     // queries
#define NC     80       // classes
#define QC     80000    // NQ*NC
#define K      300      // top-k
#define NV     (QC / 4) // 20000 float4 per batch

#define SLICES    8
#define SLICE_F4  (NV / SLICES)   // 2500 float4 per slice
#define SLICE_CAP 384
#define RCAP      1024            // candidate capacity in rank kernel
#define NBINS     4096

#define NTH1  256   // scan kernel threads
#define NTH2  512   // rank kernel threads

#define THRESH 2.576f   // P(N(0,1)>2.576) ~ 0.5% -> ~400 cands/batch

// global scratch (allowed: __device__ arrays, no allocation)
__device__ unsigned long long g_cand[NB][SLICES][SLICE_CAP];
__device__ unsigned           g_scnt[NB][SLICES];

// order-preserving float -> uint key (larger key == larger float)
__device__ __forceinline__ unsigned key_of(float x) {
    unsigned u = __float_as_uint(x);
    return (u & 0x80000000u) ? ~u : (u | 0x80000000u);
}
__device__ __forceinline__ float val_of(unsigned k) {
    unsigned u = (k & 0x80000000u) ? (k ^ 0x80000000u) : ~k;
    return __uint_as_float(u);
}

// ---------------- kernel 1: sliced threshold scan (at HBM roofline) ----------------
__global__ __launch_bounds__(NTH1)
void scan_kernel(const float* __restrict__ logits)
{
    __shared__ unsigned s_cnt;
    const int b   = blockIdx.x >> 3;        // batch
    const int s   = blockIdx.x & 7;         // slice
    const int tid = threadIdx.x;

    if (tid == 0) s_cnt = 0;
    __syncthreads();

    const float4* base = (const float4*)(logits + (size_t)b * QC) + s * SLICE_F4;

    #pragma unroll 5
    for (int i = tid; i < SLICE_F4; i += NTH1) {
        float4 v = base[i];
        float m01 = fmaxf(v.x, v.y);
        float m23 = fmaxf(v.z, v.w);
        if (fmaxf(m01, m23) > THRESH) {          // rare (~2% of iters)
            float xs[4] = {v.x, v.y, v.z, v.w};
            #pragma unroll
            for (int j = 0; j < 4; j++) {
                if (xs[j] > THRESH) {
                    unsigned p = atomicAdd(&s_cnt, 1u);
                    if (p < SLICE_CAP) {
                        unsigned idx = 4u * (unsigned)(s * SLICE_F4 + i) + (unsigned)j;
                        g_cand[b][s][p] = ((unsigned long long)key_of(xs[j]) << 32)
                                        | (unsigned long long)(~idx);
                    }
                }
            }
        }
    }
    __syncthreads();
    if (tid == 0) g_scnt[b][s] = s_cnt;
}

// ---------------- kernel 2: gather + histogram-rank + epilogue ----------------
__global__ __launch_bounds__(NTH2)
void rank_kernel(const float* __restrict__ logits,
                 const float* __restrict__ boxes,
                 const float* __restrict__ sizes,
                 float* __restrict__ out)
{
    __shared__ unsigned long long cand[RCAP];
    __shared__ unsigned long long scat[RCAP];
    __shared__ unsigned cnt_ge[NBINS + 1];
    __shared__ unsigned scan_s[NTH2];
    __shared__ unsigned offs[SLICES + 1];
    __shared__ unsigned cnts[SLICES];
    __shared__ int      s_bad;
    __shared__ unsigned s_cnt;
    __shared__ unsigned s_kmax;

    const int b   = blockIdx.x;
    const int tid = threadIdx.x;
    unsigned M;
    unsigned kmin = key_of(THRESH);

    if (tid == 0) {
        unsigned sum = 0; int bad = 0;
        #pragma unroll
        for (int s = 0; s < SLICES; s++) {
            unsigned c = g_scnt[b][s];
            if (c > SLICE_CAP) bad = 1;
            cnts[s] = min(c, (unsigned)SLICE_CAP);
            offs[s] = sum;
            sum += cnts[s];
        }
        offs[SLICES] = sum;
        if (sum < K || sum > RCAP) bad = 1;
        s_bad = bad;
        s_kmax = 0;
    }
    __syncthreads();

    if (!s_bad) {
        // gather candidate slices into contiguous smem (tiny; L2-resident)
        #pragma unroll
        for (int s = 0; s < SLICES; s++) {
            unsigned c = cnts[s], o = offs[s];
            for (unsigned i = tid; i < c; i += NTH2)
                cand[o + i] = g_cand[b][s][i];
        }
        M = offs[SLICES];
        __syncthreads();
    } else {
        // fallback: full-batch bisection rescan (correct for any distribution)
        const float4* base = (const float4*)(logits + (size_t)b * QC);
        unsigned lo_key = 0u, hi_key = 0xFFFFFFFFu;
        unsigned cur = kmin;
        M = 0;
        for (int attempt = 0; attempt < 34; attempt++) {
            if (tid == 0) s_cnt = 0;
            __syncthreads();
            const float t = val_of(cur);
            for (int i = tid; i < NV; i += NTH2) {
                float4 v = base[i];
                float m01 = fmaxf(v.x, v.y);
                float m23 = fmaxf(v.z, v.w);
                if (fmaxf(m01, m23) > t) {
                    float xs[4] = {v.x, v.y, v.z, v.w};
                    #pragma unroll
                    for (int j = 0; j < 4; j++) {
                        if (xs[j] > t) {
                            unsigned p = atomicAdd(&s_cnt, 1u);
                            if (p < RCAP) {
                                unsigned idx = 4u * (unsigned)i + (unsigned)j;
                                cand[p] = ((unsigned long long)key_of(xs[j]) << 32)
                                        | (unsigned long long)(~idx);
                            }
                        }
                    }
                }
            }
            __syncthreads();
            unsigned tot = s_cnt;
            if (tot >= K && tot <= RCAP) { M = tot; kmin = cur; break; }
            __syncthreads();
            if (tot > RCAP) { lo_key = cur; cur = cur + ((hi_key - cur) >> 1); }
            else            { hi_key = cur; cur = lo_key + ((cur - lo_key) >> 1); }
        }
        if (M == 0) { M = min(s_cnt, (unsigned)RCAP); kmin = 0u; }  // exhausted: clamp
        __syncthreads();
    }

    // ---- adaptive bin width: shift so (kmax-kmin)>>shift < NBINS ----
    {
        unsigned km = 0;
        for (unsigned i = tid; i < M; i += NTH2)
            km = max(km, (unsigned)(cand[i] >> 32));
        km = __reduce_max_sync(0xFFFFFFFFu, km);
        if ((tid & 31) == 0) atomicMax(&s_kmax, km);
    }
    // zero histogram while the reduction settles
    for (int i = tid; i < NBINS + 1; i += NTH2) cnt_ge[i] = 0;
    __syncthreads();

    unsigned range = s_kmax - kmin;
    if (range == 0) range = 1;
    int shift = 32 - __clz(range) - 12;   // (range>>shift) <= 4095
    if (shift < 0) shift = 0;

    // ---- histogram (spread atomics over ~M distinct bins) ----
    for (unsigned i = tid; i < M; i += NTH2) {
        unsigned key = (unsigned)(cand[i] >> 32);
        unsigned bin = min((key - kmin) >> shift, (unsigned)(NBINS - 1));
        atomicAdd(&cnt_ge[bin], 1u);
    }
    __syncthreads();

    // ---- suffix scan: cnt_ge[b] = # candidates with bin >= b ----
    unsigned vals[NBINS / NTH2];          // 8 bins per thread
    unsigned csum = 0;
    #pragma unroll
    for (int j = 0; j < NBINS / NTH2; j++) {
        vals[j] = cnt_ge[tid * (NBINS / NTH2) + j];
        csum += vals[j];
    }
    scan_s[tid] = csum;
    __syncthreads();
    for (int d = 1; d < NTH2; d <<= 1) {
        unsigned add = (tid + d < NTH2) ? scan_s[tid + d] : 0u;
        __syncthreads();
        scan_s[tid] += add;
        __syncthreads();
    }
    {
        unsigned running = (tid + 1 < NTH2) ? scan_s[tid + 1] : 0u;
        #pragma unroll
        for (int j = NBINS / NTH2 - 1; j >= 0; j--) {
            unsigned t2 = vals[j];
            cnt_ge[tid * (NBINS / NTH2) + j] = running + t2;
            running += t2;
        }
    }
    if (tid == 0) cnt_ge[NBINS] = 0;
    __syncthreads();

    // ---- per-candidate base/cnt (pre-atomic reads), max 2 cands/thread ----
    unsigned long long comp[2];
    unsigned basep[2], cntb[2], binv[2];
    bool act[2];
    #pragma unroll
    for (int h = 0; h < 2; h++) {
        unsigned i = (unsigned)tid + h * NTH2;
        act[h] = (i < M);
        if (act[h]) {
            comp[h] = cand[i];
            unsigned key = (unsigned)(comp[h] >> 32);
            unsigned bin = min((key - kmin) >> shift, (unsigned)(NBINS - 1));
            binv[h]  = bin;
            basep[h] = cnt_ge[bin + 1];            // # in strictly higher bins
            cntb[h]  = cnt_ge[bin] - basep[h];     // # in my bin
        }
    }
    __syncthreads();

    // ---- scatter into bin-grouped order: slot = atomicAdd(cnt_ge[bin+1]) ----
    #pragma unroll
    for (int h = 0; h < 2; h++) {
        if (act[h]) {
            unsigned p = atomicAdd(&cnt_ge[binv[h] + 1], 1u);  // in [base, base+cntb)
            scat[p] = comp[h];
        }
    }
    __syncthreads();

    // ---- exact rank = base + #{same-bin composites > mine}; emit if < K ----
    const float w = sizes[2 * b], h2 = sizes[2 * b + 1];
    #pragma unroll
    for (int h = 0; h < 2; h++) {
        if (act[h] && basep[h] < K) {
            unsigned r = basep[h];
            unsigned e = basep[h] + cntb[h];
            for (unsigned j = basep[h]; j < e; j++)
                r += (scat[j] > comp[h]);
            if (r < K) {
                unsigned kk  = (unsigned)(comp[h] >> 32);
                unsigned idx = ~(unsigned)comp[h];
                float x = val_of(kk);
                float score = 1.0f / (1.0f + expf(-x));
                int label = (int)(idx % NC);
                int q     = (int)(idx / NC);

                float4 bx = ((const float4*)(boxes + ((size_t)b * NQ + q) * 4))[0];
                float hw = 0.5f * bx.z, hh = 0.5f * bx.w;

                int o = b * K + (int)r;
                out[o] = (float)label;                     // labels [B,K]
                float* ob = out + NB * K + (size_t)o * 4;  // boxes  [B,K,4]
                ob[0] = (bx.x - hw) * w;
                ob[1] = (bx.y - hh) * h2;
                ob[2] = (bx.x + hw) * w;
                ob[3] = (bx.y + hh) * h2;
                out[(size_t)NB * K * 5 + o] = score;       // scores [B,K]
            }
        }
    }
}

extern "C" void kernel_launch(void* const* d_in, const int* in_sizes, int n_in,
                              void* d_out, int out_size) {
    const float* logits = (const float*)d_in[0];
    const float* boxes  = (const float*)d_in[1];
    const float* sizes  = (const float*)d_in[2];
    float* out = (float*)d_out;
    scan_kernel<<<NB * SLICES, NTH1>>>(logits);
    rank_kernel<<<NB, NTH2>>>(logits, boxes, sizes, out);
}